// round 9
// baseline (speedup 1.0000x reference)
#include <cuda_runtime.h>
#include <cuda_bf16.h>
#include <math.h>
#include <stdint.h>

#define BB   256   // batch
#define CC   256   // channels
#define TT   256   // tokens (16x16)
#define NH   8
#define HD   32
#define META 256
#define OC3  768

// ---------------- scratch (device globals; no runtime allocation) ----------
__device__ float g_q[(size_t)BB * NH * TT * HD];     // [b][h][t][d]
__device__ float g_k[(size_t)BB * NH * TT * HD];
__device__ float g_v[(size_t)BB * NH * TT * HD];
__device__ float g_ao[(size_t)BB * CC * TT];         // [b][c][t]
__device__ float g_biasT[(size_t)NH * TT * TT];      // [h][key][query]
__device__ float g_biasMax[NH * TT];                 // max over key, per (h,query)

// =================== warp-MMA building blocks (sm_80-level PTX) ============
__device__ __forceinline__ uint32_t smem_u32(const void* p) {
    uint32_t a;
    asm("{ .reg .u64 t; cvta.to.shared.u64 t, %1; cvt.u32.u64 %0, t; }"
        : "=r"(a) : "l"(p));
    return a;
}
__device__ __forceinline__ void ldsm_x4(uint32_t r[4], uint32_t addr) {
    asm volatile("ldmatrix.sync.aligned.m8n8.x4.shared.b16 {%0,%1,%2,%3}, [%4];"
                 : "=r"(r[0]), "=r"(r[1]), "=r"(r[2]), "=r"(r[3]) : "r"(addr));
}
__device__ __forceinline__ void ldsm_x2(uint32_t r[2], uint32_t addr) {
    asm volatile("ldmatrix.sync.aligned.m8n8.x2.shared.b16 {%0,%1}, [%2];"
                 : "=r"(r[0]), "=r"(r[1]) : "r"(addr));
}
__device__ __forceinline__ void mma_bf16(float* d, const uint32_t* a, const uint32_t* b) {
    asm volatile(
        "mma.sync.aligned.m16n8k16.row.col.f32.bf16.bf16.f32 "
        "{%0,%1,%2,%3}, {%4,%5,%6,%7}, {%8,%9}, {%0,%1,%2,%3};"
        : "+f"(d[0]), "+f"(d[1]), "+f"(d[2]), "+f"(d[3])
        : "r"(a[0]), "r"(a[1]), "r"(a[2]), "r"(a[3]), "r"(b[0]), "r"(b[1]));
}

#define KC   32    // K chunk
#define ASTR 40    // smem row stride in halves (80 B: 16B-aligned, conflict-free)

// split v into hi (bf16) + lo (bf16 of residual)
__device__ __forceinline__ void bf16_split(float v, uint16_t& h, uint16_t& l) {
    __nv_bfloat16 hb = __float2bfloat16_rn(v);
    float r = v - __bfloat162float(hb);
    __nv_bfloat16 lb = __float2bfloat16_rn(r);
    h = __bfloat16_as_ushort(hb);
    l = __bfloat16_as_ushort(lb);
}

// Transpose loader: src fp32 [KC rows k][ldm cols], take cols [0,128) -> dst[m][k]
__device__ __forceinline__ void load_T(uint16_t* hi, uint16_t* lo,
                                       const float* src, int ldm, int tid) {
#pragma unroll
    for (int s = 0; s < 4; s++) {
        int item = tid + s * 256;
        int k  = item >> 5;
        int mq = item & 31;
        float4 v = *(const float4*)(src + (size_t)k * ldm + mq * 4);
        uint16_t h, l;
        bf16_split(v.x, h, l); hi[(mq*4+0)*ASTR + k] = h; lo[(mq*4+0)*ASTR + k] = l;
        bf16_split(v.y, h, l); hi[(mq*4+1)*ASTR + k] = h; lo[(mq*4+1)*ASTR + k] = l;
        bf16_split(v.z, h, l); hi[(mq*4+2)*ASTR + k] = h; lo[(mq*4+2)*ASTR + k] = l;
        bf16_split(v.w, h, l); hi[(mq*4+3)*ASTR + k] = h; lo[(mq*4+3)*ASTR + k] = l;
    }
}

// Direct loader: src fp32 [128 rows][ldk], take cols [0,KC) -> dst[row][k]
__device__ __forceinline__ void load_D(uint16_t* hi, uint16_t* lo,
                                       const float* src, int ldk, int tid) {
#pragma unroll
    for (int s = 0; s < 4; s++) {
        int item = tid + s * 256;
        int n  = item >> 3;
        int kq = item & 7;
        float4 v = *(const float4*)(src + (size_t)n * ldk + kq * 4);
        uint16_t h0, l0, h1, l1;
        bf16_split(v.x, h0, l0); bf16_split(v.y, h1, l1);
        *(uint32_t*)(hi + n*ASTR + kq*4)     = (uint32_t)h0 | ((uint32_t)h1 << 16);
        *(uint32_t*)(lo + n*ASTR + kq*4)     = (uint32_t)l0 | ((uint32_t)l1 << 16);
        bf16_split(v.z, h0, l0); bf16_split(v.w, h1, l1);
        *(uint32_t*)(hi + n*ASTR + kq*4 + 2) = (uint32_t)h0 | ((uint32_t)h1 << 16);
        *(uint32_t*)(lo + n*ASTR + kq*4 + 2) = (uint32_t)l0 | ((uint32_t)l1 << 16);
    }
}

// One K-chunk of warp MMAs: 2 k16 steps, 3 split passes each.
__device__ __forceinline__ void mma_chunk(
    uint32_t aAh, uint32_t aAl, uint32_t aBh, uint32_t aBl,
    int warpm, int warpn, int lane, float acc[4][4][4])
{
    const int arow  = warpm * 64 + (lane & 15);
    const int akoff = (lane >> 4) * 8;
    const int brow  = warpn * 32 + (lane & 7);
    const int bkoff = ((lane >> 3) & 1) * 8;
#pragma unroll
    for (int kk = 0; kk < KC; kk += 16) {
        uint32_t ah[4][4], al[4][4], bh[4][2], bl[4][2];
#pragma unroll
        for (int mt = 0; mt < 4; mt++) {
            uint32_t off = (uint32_t)((arow + mt * 16) * ASTR + kk + akoff) * 2;
            ldsm_x4(ah[mt], aAh + off);
            ldsm_x4(al[mt], aAl + off);
        }
#pragma unroll
        for (int nt = 0; nt < 4; nt++) {
            uint32_t off = (uint32_t)((brow + nt * 8) * ASTR + kk + bkoff) * 2;
            ldsm_x2(bh[nt], aBh + off);
            ldsm_x2(bl[nt], aBl + off);
        }
#pragma unroll
        for (int mt = 0; mt < 4; mt++)
#pragma unroll
            for (int nt = 0; nt < 4; nt++) {
                mma_bf16(acc[mt][nt], ah[mt], bh[nt]);
                mma_bf16(acc[mt][nt], ah[mt], bl[nt]);
                mma_bf16(acc[mt][nt], al[mt], bh[nt]);
            }
    }
}

// ---------------------------------------------------------------------------
// Kernel 1: relative-position-bias MLP (transposed store: [h][key][query])
// ---------------------------------------------------------------------------
__global__ __launch_bounds__(256) void bias_kernel(
    const float* __restrict__ mw1, const float* __restrict__ mb1,
    const float* __restrict__ mw2, const float* __restrict__ mb2)
{
    __shared__ float s_w1[META * 2];
    __shared__ float s_b1[META];
    __shared__ float s_w2[NH * META];
    __shared__ float s_b2[NH];
    for (int i = threadIdx.x; i < META * 2; i += 256) s_w1[i] = mw1[i];
    for (int i = threadIdx.x; i < META;     i += 256) s_b1[i] = mb1[i];
    for (int i = threadIdx.x; i < NH * META; i += 256) s_w2[i] = mw2[i];
    if (threadIdx.x < NH) s_b2[threadIdx.x] = mb2[threadIdx.x];
    __syncthreads();

    int idx = blockIdx.x * 256 + threadIdx.x;
    int q  = idx & (TT - 1);
    int kk = idx >> 8;

    float d0 = (float)((q >> 4) - (kk >> 4));
    float d1 = (float)((q & 15) - (kk & 15));
    float r0 = copysignf(log1pf(fabsf(d0)), d0);
    float r1 = copysignf(log1pf(fabsf(d1)), d1);

    float acc[NH];
#pragma unroll
    for (int h = 0; h < NH; h++) acc[h] = s_b2[h];

    for (int j = 0; j < META; j++) {
        float hj = fmaf(r0, s_w1[2 * j], fmaf(r1, s_w1[2 * j + 1], s_b1[j]));
        hj = fmaxf(hj, 0.0f);
#pragma unroll
        for (int h = 0; h < NH; h++)
            acc[h] = fmaf(hj, s_w2[h * META + j], acc[h]);
    }
#pragma unroll
    for (int h = 0; h < NH; h++)
        g_biasT[(size_t)h * TT * TT + (size_t)kk * TT + q] = acc[h];
}

// Kernel 1b: per-(h,q) max over keys of the bias table.
__global__ __launch_bounds__(256) void biasmax_kernel()
{
    int h = blockIdx.x;
    int q = threadIdx.x;
    const float* p = g_biasT + (size_t)h * TT * TT + q;
    float m = -1e30f;
#pragma unroll 8
    for (int k = 0; k < TT; k++)
        m = fmaxf(m, p[(size_t)k * TT]);
    g_biasMax[h * TT + q] = m;
}

// ---------------------------------------------------------------------------
// Kernel 2: QKV GEMM on mma.sync (bf16 hi/lo split).
// out[t][oc] = sum_c x^T[t][c] * w[oc][c] + b[oc]
// A = x^T (transpose load), B = w (direct [n][k]).  CTA 128(t) x 128(oc).
// ---------------------------------------------------------------------------
__global__ __launch_bounds__(256) void qkv_mma_kernel(
    const float* __restrict__ x, const float* __restrict__ w,
    const float* __restrict__ bq)
{
    __shared__ __align__(16) uint16_t sAh[128 * ASTR];
    __shared__ __align__(16) uint16_t sAl[128 * ASTR];
    __shared__ __align__(16) uint16_t sBh[128 * ASTR];
    __shared__ __align__(16) uint16_t sBl[128 * ASTR];

    const int tid   = threadIdx.x;
    const int lane  = tid & 31;
    const int wid   = tid >> 5;
    const int warpm = wid >> 2;
    const int warpn = wid & 3;

    const int my = blockIdx.y;
    const int b  = my >> 1;
    const int t0 = (my & 1) << 7;
    const int n0 = blockIdx.x << 7;
    const float* xb = x + (size_t)b * CC * TT;

    const uint32_t aAh = smem_u32(sAh), aAl = smem_u32(sAl);
    const uint32_t aBh = smem_u32(sBh), aBl = smem_u32(sBl);

    float acc[4][4][4];
#pragma unroll
    for (int mt = 0; mt < 4; mt++)
#pragma unroll
        for (int nt = 0; nt < 4; nt++)
#pragma unroll
            for (int i = 0; i < 4; i++) acc[mt][nt][i] = 0.0f;

    for (int c0 = 0; c0 < CC; c0 += KC) {
        load_T(sAh, sAl, xb + (size_t)c0 * TT + t0, TT, tid);
        load_D(sBh, sBl, w + (size_t)n0 * CC + c0, CC, tid);
        __syncthreads();
        mma_chunk(aAh, aAl, aBh, aBl, warpm, warpn, lane, acc);
        __syncthreads();
    }

    // Epilogue: pairs (oc, oc+1) contiguous in g_* [t][d] layout.
    const int g   = lane >> 2;
    const int tig = lane & 3;
    const int s   = n0 >> 8;               // tile never crosses q/k/v boundary
    float* dstb = (s == 0) ? g_q : (s == 1) ? g_k : g_v;

#pragma unroll
    for (int nt = 0; nt < 4; nt++) {
        const int oc = n0 + warpn * 32 + nt * 8 + tig * 2;
        const int ch = oc & (CC - 1);
        const int h  = ch >> 5;
        const int d  = ch & (HD - 1);
        const float b0 = bq[oc], b1 = bq[oc + 1];
        float* base = dstb + ((size_t)b * NH + h) * TT * HD + d;
#pragma unroll
        for (int mt = 0; mt < 4; mt++) {
            const int t = t0 + warpm * 64 + mt * 16 + g;
            float2 o0 = make_float2(acc[mt][nt][0] + b0, acc[mt][nt][1] + b1);
            float2 o1 = make_float2(acc[mt][nt][2] + b0, acc[mt][nt][3] + b1);
            *(float2*)(base + (size_t)t * HD)       = o0;
            *(float2*)(base + (size_t)(t + 8) * HD) = o1;
        }
    }
}

// Kernel 2b: normalize q rows by rsqrt(|q|^2)/tau and k rows by rsqrt(|k|^2).
#define NROWS (BB * NH * TT)
__global__ __launch_bounds__(256) void qkscale_kernel(const float* __restrict__ tau)
{
    int row = blockIdx.x * 256 + threadIdx.x;     // [0, 2*NROWS)
    int isq = (row < NROWS);
    int r   = isq ? row : row - NROWS;
    int h   = (r >> 8) & (NH - 1);
    float* p = (isq ? g_q : g_k) + (size_t)r * HD;
    float4 v[8];
    float s2 = 0.0f;
#pragma unroll
    for (int i = 0; i < 8; i++) {
        v[i] = *(const float4*)(p + i * 4);
        s2 = fmaf(v[i].x, v[i].x, s2);
        s2 = fmaf(v[i].y, v[i].y, s2);
        s2 = fmaf(v[i].z, v[i].z, s2);
        s2 = fmaf(v[i].w, v[i].w, s2);
    }
    float sc = rsqrtf(fmaxf(s2, 1e-12f));
    if (isq) sc /= fmaxf(tau[h], 0.01f);
#pragma unroll
    for (int i = 0; i < 8; i++) {
        v[i].x *= sc; v[i].y *= sc; v[i].z *= sc; v[i].w *= sc;
        *(float4*)(p + i * 4) = v[i];
    }
}

// ---------------------------------------------------------------------------
// Kernel 3: attention, branch-free fixed-shift softmax (unchanged).
// ---------------------------------------------------------------------------
#define KSTAGE 128
#define KP     36

__global__ __launch_bounds__(128, 2) void attn_kernel(const float* __restrict__ tau)
{
    __shared__ float ks[KSTAGE * KP];
    __shared__ float vs[KSTAGE * KP];

    const int tid = threadIdx.x;
    const int bh  = blockIdx.x;
    const int b   = bh >> 3;
    const int h   = bh & 7;
    const size_t base = (size_t)bh * TT * HD;

    float q0[HD], q1[HD], a0[HD], a1[HD];
    {
        const float4* qr0 = (const float4*)(g_q + base + (size_t)tid * HD);
        const float4* qr1 = (const float4*)(g_q + base + (size_t)(tid + 128) * HD);
#pragma unroll
        for (int i = 0; i < 8; i++) {
            float4 t4 = qr0[i];
            q0[4*i+0] = t4.x; q0[4*i+1] = t4.y; q0[4*i+2] = t4.z; q0[4*i+3] = t4.w;
            float4 u4 = qr1[i];
            q1[4*i+0] = u4.x; q1[4*i+1] = u4.y; q1[4*i+2] = u4.z; q1[4*i+3] = u4.w;
        }
    }
#pragma unroll
    for (int d = 0; d < HD; d++) { a0[d] = 0.0f; a1[d] = 0.0f; }

    const float inv_tau = 1.0f / fmaxf(tau[h], 0.01f);
    const float M0 = g_biasMax[h * TT + tid]       + inv_tau;
    const float M1 = g_biasMax[h * TT + tid + 128] + inv_tau;
    const float* brow0 = g_biasT + (size_t)h * TT * TT + tid;
    const float* brow1 = brow0 + 128;

    float l0 = 0.0f, l1 = 0.0f;

    for (int j0 = 0; j0 < TT; j0 += KSTAGE) {
        __syncthreads();
        const float4* kg4 = (const float4*)(g_k + base + (size_t)j0 * HD);
        const float4* vg4 = (const float4*)(g_v + base + (size_t)j0 * HD);
#pragma unroll
        for (int it = 0; it < 8; it++) {
            int i = tid + it * 128;
            int r = i >> 3, c = i & 7;
            *(float4*)(ks + r * KP + c * 4) = kg4[i];
            *(float4*)(vs + r * KP + c * 4) = vg4[i];
        }
        __syncthreads();

#pragma unroll 2
        for (int j = 0; j < KSTAGE; j++) {
            const float4* kr = (const float4*)(ks + j * KP);
            float p00 = 0.f, p01 = 0.f, p02 = 0.f, p03 = 0.f;
            float p10 = 0.f, p11 = 0.f, p12 = 0.f, p13 = 0.f;
#pragma unroll
            for (int d4 = 0; d4 < 8; d4++) {
                float4 kv = kr[d4];
                p00 = fmaf(q0[4*d4+0], kv.x, p00);
                p01 = fmaf(q0[4*d4+1], kv.y, p01);
                p02 = fmaf(q0[4*d4+2], kv.z, p02);
                p03 = fmaf(q0[4*d4+3], kv.w, p03);
                p10 = fmaf(q1[4*d4+0], kv.x, p10);
                p11 = fmaf(q1[4*d4+1], kv.y, p11);
                p12 = fmaf(q1[4*d4+2], kv.z, p12);
                p13 = fmaf(q1[4*d4+3], kv.w, p13);
            }
            float bias0 = brow0[(size_t)(j0 + j) * TT];
            float bias1 = brow1[(size_t)(j0 + j) * TT];
            float e0 = __expf(((p00 + p01) + (p02 + p03)) + (bias0 - M0));
            float e1 = __expf(((p10 + p11) + (p12 + p13)) + (bias1 - M1));
            l0 += e0;
            l1 += e1;

            const float4* vr = (const float4*)(vs + j * KP);
#pragma unroll
            for (int d4 = 0; d4 < 8; d4++) {
                float4 vv = vr[d4];
                a0[4*d4+0] = fmaf(e0, vv.x, a0[4*d4+0]);
                a0[4*d4+1] = fmaf(e0, vv.y, a0[4*d4+1]);
                a0[4*d4+2] = fmaf(e0, vv.z, a0[4*d4+2]);
                a0[4*d4+3] = fmaf(e0, vv.w, a0[4*d4+3]);
                a1[4*d4+0] = fmaf(e1, vv.x, a1[4*d4+0]);
                a1[4*d4+1] = fmaf(e1, vv.y, a1[4*d4+1]);
                a1[4*d4+2] = fmaf(e1, vv.z, a1[4*d4+2]);
                a1[4*d4+3] = fmaf(e1, vv.w, a1[4*d4+3]);
            }
        }
    }

    const float il0 = 1.0f / l0;
    const float il1 = 1.0f / l1;
    float* ob0 = g_ao + ((size_t)b * CC + h * HD) * TT + tid;
    float* ob1 = ob0 + 128;
#pragma unroll
    for (int d = 0; d < HD; d++) {
        ob0[(size_t)d * TT] = a0[d] * il0;
        ob1[(size_t)d * TT] = a1[d] * il1;
    }
}

// ---------------------------------------------------------------------------
// Kernel 4: proj GEMM on mma.sync.
// out[b][co][t] = sum_ci w[co][ci] * ao[b][ci][t] + bp[co]
// A = w (direct [m][k]), B = ao (transpose load: [k][n] -> [n][k]).
// CTA: 128(co) x 128(t).  Epilogue [m][n] == [co][t] contiguous.
// ---------------------------------------------------------------------------
__global__ __launch_bounds__(256) void proj_mma_kernel(
    const float* __restrict__ w, const float* __restrict__ bp,
    float* __restrict__ out)
{
    __shared__ __align__(16) uint16_t sAh[128 * ASTR];
    __shared__ __align__(16) uint16_t sAl[128 * ASTR];
    __shared__ __align__(16) uint16_t sBh[128 * ASTR];
    __shared__ __align__(16) uint16_t sBl[128 * ASTR];

    const int tid   = threadIdx.x;
    const int lane  = tid & 31;
    const int wid   = tid >> 5;
    const int warpm = wid >> 2;
    const int warpn = wid & 3;

    const int my = blockIdx.y;
    const int b  = my >> 1;
    const int m0 = (my & 1) << 7;          // co tile
    const int t0 = blockIdx.x << 7;        // t tile
    const float* ab = g_ao + (size_t)b * CC * TT;

    const uint32_t aAh = smem_u32(sAh), aAl = smem_u32(sAl);
    const uint32_t aBh = smem_u32(sBh), aBl = smem_u32(sBl);

    float acc[4][4][4];
#pragma unroll
    for (int mt = 0; mt < 4; mt++)
#pragma unroll
        for (int nt = 0; nt < 4; nt++)
#pragma unroll
            for (int i = 0; i < 4; i++) acc[mt][nt][i] = 0.0f;

    for (int c0 = 0; c0 < CC; c0 += KC) {
        load_D(sAh, sAl, w + (size_t)m0 * CC + c0, CC, tid);
        load_T(sBh, sBl, ab + (size_t)c0 * TT + t0, TT, tid);
        __syncthreads();
        mma_chunk(aAh, aAl, aBh, aBl, warpm, warpn, lane, acc);
        __syncthreads();
    }

    const int g   = lane >> 2;
    const int tig = lane & 3;
#pragma unroll
    for (int mt = 0; mt < 4; mt++) {
        const int co = m0 + warpm * 64 + mt * 16 + g;
        const float bp0 = bp[co], bp8 = bp[co + 8];
        float* r0 = out + ((size_t)b * CC + co) * TT;
        float* r8 = r0 + (size_t)8 * TT;
#pragma unroll
        for (int nt = 0; nt < 4; nt++) {
            const int t = t0 + warpn * 32 + nt * 8 + tig * 2;
            *(float2*)(r0 + t) = make_float2(acc[mt][nt][0] + bp0, acc[mt][nt][1] + bp0);
            *(float2*)(r8 + t) = make_float2(acc[mt][nt][2] + bp8, acc[mt][nt][3] + bp8);
        }
    }
}

// ---------------------------------------------------------------------------
extern "C" void kernel_launch(void* const* d_in, const int* in_sizes, int n_in,
                              void* d_out, int out_size)
{
    const float* x      = (const float*)d_in[0];
    const float* w_qkv  = (const float*)d_in[1];
    const float* b_qkv  = (const float*)d_in[2];
    const float* w_proj = (const float*)d_in[3];
    const float* b_proj = (const float*)d_in[4];
    const float* mw1    = (const float*)d_in[5];
    const float* mb1    = (const float*)d_in[6];
    const float* mw2    = (const float*)d_in[7];
    const float* mb2    = (const float*)d_in[8];
    const float* tau    = (const float*)d_in[9];
    float* out = (float*)d_out;

    bias_kernel<<<TT * TT / 256, 256>>>(mw1, mb1, mw2, mb2);
    biasmax_kernel<<<NH, 256>>>();
    qkv_mma_kernel<<<dim3(OC3 / 128, BB * TT / 128), 256>>>(x, w_qkv, b_qkv);
    qkscale_kernel<<<2 * NROWS / 256, 256>>>(tau);
    attn_kernel<<<BB * NH, 128>>>(tau);
    proj_mma_kernel<<<dim3(TT / 128, BB * CC / 128), 256>>>(w_proj, b_proj, out);
}